// round 3
// baseline (speedup 1.0000x reference)
#include <cuda_runtime.h>
#include <cstdint>

#define D       128
#define H       64
#define ALPHA   0.2f
#define LN_EPS  1e-5f
#define MAXN    131072

// Scratch (device globals: allocation-free per harness rules). 16B-aligned for
// float4 stores and red.global.add.v4.
__device__ __align__(16) float g_msg[(size_t)MAXN * D];
__device__ float g_cnt[MAXN];

__device__ __forceinline__ float2 ffma2(float2 a, float2 b, float2 c) {
    unsigned long long au = *reinterpret_cast<unsigned long long*>(&a);
    unsigned long long bu = *reinterpret_cast<unsigned long long*>(&b);
    unsigned long long cu = *reinterpret_cast<unsigned long long*>(&c);
    unsigned long long du;
    asm("fma.rn.f32x2 %0, %1, %2, %3;" : "=l"(du) : "l"(au), "l"(bu), "l"(cu));
    return *reinterpret_cast<float2*>(&du);
}

__global__ void k_zero(int N) {
    int i = blockIdx.x * blockDim.x + threadIdx.x;
    if (i < N * 32) reinterpret_cast<float4*>(g_msg)[i] = make_float4(0.f, 0.f, 0.f, 0.f);
    if (i < N) g_cnt[i] = 0.f;
}

// One warp per edge: gather x[src] (512B, float4/lane), vector-reduce into msg[dst].
// edge_index is int32 (JAX demotes int64 without x64 mode). Clamp defensively.
__global__ void __launch_bounds__(256) k_edges(const float* __restrict__ x,
                                               const int* __restrict__ ei, int E, int N) {
    int e = (blockIdx.x * 256 + threadIdx.x) >> 5;
    if (e >= E) return;
    int lane = threadIdx.x & 31;
    int src = ei[e];
    int dst = ei[E + e];
    src = min(max(src, 0), N - 1);
    dst = min(max(dst, 0), N - 1);
    float4 v = reinterpret_cast<const float4*>(x + (size_t)src * D)[lane];
    float* m = g_msg + (size_t)dst * D + lane * 4;
    asm volatile("red.global.add.v4.f32 [%0], {%1, %2, %3, %4};"
                 :: "l"(m), "f"(v.x), "f"(v.y), "f"(v.z), "f"(v.w) : "memory");
    if (lane == 0) atomicAdd(&g_cnt[dst], 1.0f);
}

// Fused node kernel: local_mean + tanh(||x-lm||) + MLP (f32x2 packed, 4 nodes/warp)
// + residual + LayerNorm. 8 warps/block, weights staged in shared, persistent grid.
__global__ void __launch_bounds__(256, 2) k_nodes(
    const float* __restrict__ x,
    const float* __restrict__ W1, const float* __restrict__ b1,
    const float* __restrict__ W2, const float* __restrict__ b2,
    const float* __restrict__ gamma, const float* __restrict__ beta,
    float* __restrict__ out, int N)
{
    extern __shared__ float smem[];
    float* sW1 = smem;                 // 128*64
    float* sW2 = sW1 + D * H;          // 64*128
    float* sb1 = sW2 + H * D;          // 64
    float* sb2 = sb1 + H;              // 128
    float* sg  = sb2 + D;              // 128
    float* sbt = sg + D;               // 128
    float* sxT = sbt + D;              // 8 warps * 128 * 4  (x transposed [k][node])
    float* shT = sxT + 8 * D * 4;      // 8 warps * 64 * 4   (hidden transposed)

    int tid = threadIdx.x;
    for (int i = tid; i < D * H; i += 256) sW1[i] = W1[i];
    for (int i = tid; i < H * D; i += 256) sW2[i] = W2[i];
    if (tid < H) sb1[tid] = b1[tid];
    if (tid < D) { sb2[tid] = b2[tid]; sg[tid] = gamma[tid]; sbt[tid] = beta[tid]; }
    __syncthreads();

    int w = tid >> 5, lane = tid & 31;
    int nn = lane >> 3, c = lane & 7;     // lane group: 4 nodes x 8 chunk-lanes
    float* myxT = sxT + w * (D * 4);
    float* myhT = shT + w * (H * 4);

    for (int base = blockIdx.x * 32 + w * 4; base < N; base += gridDim.x * 32) {
        // ---- phase 1: load full x row (4 chunks/lane), local_mean, feature_diff;
        //      stage x transposed [k][node] ----
        int node = base + nn;
        bool valid = node < N;
        float inv = valid ? (1.0f / fmaxf(g_cnt[node], 1.0f)) : 0.f;
        const float4* xrow = reinterpret_cast<const float4*>(x + (size_t)node * D);
        const float4* mrow = reinterpret_cast<const float4*>(g_msg + (size_t)node * D);
        float ss = 0.f;
        #pragma unroll
        for (int u = 0; u < 4; u++) {
            int ch = c + 8 * u;               // float4 chunk index 0..31
            float4 xv = make_float4(0.f, 0.f, 0.f, 0.f);
            float4 mv = xv;
            if (valid) { xv = xrow[ch]; mv = mrow[ch]; }
            float dx = xv.x - mv.x * inv, dy = xv.y - mv.y * inv;
            float dz = xv.z - mv.z * inv, dw = xv.w - mv.w * inv;
            ss += dx * dx + dy * dy + dz * dz + dw * dw;
            myxT[(4 * ch + 0) * 4 + nn] = xv.x;
            myxT[(4 * ch + 1) * 4 + nn] = xv.y;
            myxT[(4 * ch + 2) * 4 + nn] = xv.z;
            myxT[(4 * ch + 3) * 4 + nn] = xv.w;
        }
        ss += __shfl_xor_sync(0xffffffffu, ss, 1);
        ss += __shfl_xor_sync(0xffffffffu, ss, 2);
        ss += __shfl_xor_sync(0xffffffffu, ss, 4);
        float fd = tanhf(sqrtf(ss));
        float fda0 = __shfl_sync(0xffffffffu, fd, 0);
        float fda1 = __shfl_sync(0xffffffffu, fd, 8);
        float fda2 = __shfl_sync(0xffffffffu, fd, 16);
        float fda3 = __shfl_sync(0xffffffffu, fd, 24);
        __syncwarp();

        // ---- GEMM1: hidden = relu(x@W1 + b1); lane owns cols 2*lane,2*lane+1 ----
        float2 bini = make_float2(sb1[2 * lane], sb1[2 * lane + 1]);
        float2 a0 = bini, a1 = bini, a2 = bini, a3 = bini;
        const float2* w1p = reinterpret_cast<const float2*>(sW1) + lane;
        #pragma unroll 8
        for (int k = 0; k < D; k++) {
            float2 wv = w1p[k * (H / 2)];
            float4 xb = reinterpret_cast<const float4*>(myxT)[k];  // broadcast: 4 nodes
            a0 = ffma2(make_float2(xb.x, xb.x), wv, a0);
            a1 = ffma2(make_float2(xb.y, xb.y), wv, a1);
            a2 = ffma2(make_float2(xb.z, xb.z), wv, a2);
            a3 = ffma2(make_float2(xb.w, xb.w), wv, a3);
        }
        myhT[(2 * lane) * 4 + 0] = fmaxf(a0.x, 0.f);
        myhT[(2 * lane) * 4 + 1] = fmaxf(a1.x, 0.f);
        myhT[(2 * lane) * 4 + 2] = fmaxf(a2.x, 0.f);
        myhT[(2 * lane) * 4 + 3] = fmaxf(a3.x, 0.f);
        myhT[(2 * lane + 1) * 4 + 0] = fmaxf(a0.y, 0.f);
        myhT[(2 * lane + 1) * 4 + 1] = fmaxf(a1.y, 0.f);
        myhT[(2 * lane + 1) * 4 + 2] = fmaxf(a2.y, 0.f);
        myhT[(2 * lane + 1) * 4 + 3] = fmaxf(a3.y, 0.f);
        __syncwarp();

        // ---- GEMM2: out = hidden@W2 + b2; lane owns cols 4*lane..4*lane+3 ----
        float4 b2v = reinterpret_cast<const float4*>(sb2)[lane];
        float2 o0a = make_float2(b2v.x, b2v.y), o0b = make_float2(b2v.z, b2v.w);
        float2 o1a = o0a, o1b = o0b, o2a = o0a, o2b = o0b, o3a = o0a, o3b = o0b;
        #pragma unroll 8
        for (int j = 0; j < H; j++) {
            float4 wv = reinterpret_cast<const float4*>(sW2 + j * D)[lane];
            float4 hb = reinterpret_cast<const float4*>(myhT)[j];  // broadcast: 4 nodes
            float2 wlo = make_float2(wv.x, wv.y), whi = make_float2(wv.z, wv.w);
            o0a = ffma2(make_float2(hb.x, hb.x), wlo, o0a);
            o0b = ffma2(make_float2(hb.x, hb.x), whi, o0b);
            o1a = ffma2(make_float2(hb.y, hb.y), wlo, o1a);
            o1b = ffma2(make_float2(hb.y, hb.y), whi, o1b);
            o2a = ffma2(make_float2(hb.z, hb.z), wlo, o2a);
            o2b = ffma2(make_float2(hb.z, hb.z), whi, o2b);
            o3a = ffma2(make_float2(hb.w, hb.w), wlo, o3a);
            o3b = ffma2(make_float2(hb.w, hb.w), whi, o3b);
        }

        // ---- epilogue: residual + LayerNorm, one node at a time ----
        float4 g4  = reinterpret_cast<const float4*>(sg)[lane];
        float4 be4 = reinterpret_cast<const float4*>(sbt)[lane];
        #pragma unroll
        for (int q = 0; q < 4; q++) {
            int nd = base + q;
            if (nd >= N) break;
            float fdq = (q == 0) ? fda0 : (q == 1) ? fda1 : (q == 2) ? fda2 : fda3;
            float2 oa = (q == 0) ? o0a : (q == 1) ? o1a : (q == 2) ? o2a : o3a;
            float2 ob = (q == 0) ? o0b : (q == 1) ? o1b : (q == 2) ? o2b : o3b;
            float4 xq = reinterpret_cast<const float4*>(x + (size_t)nd * D)[lane];
            float af = ALPHA * fdq;
            float4 hv;
            hv.x = xq.x + af * oa.x;
            hv.y = xq.y + af * oa.y;
            hv.z = xq.z + af * ob.x;
            hv.w = xq.w + af * ob.y;
            float s  = hv.x + hv.y + hv.z + hv.w;
            float s2 = hv.x * hv.x + hv.y * hv.y + hv.z * hv.z + hv.w * hv.w;
            #pragma unroll
            for (int o = 16; o > 0; o >>= 1) {
                s  += __shfl_xor_sync(0xffffffffu, s, o);
                s2 += __shfl_xor_sync(0xffffffffu, s2, o);
            }
            float mu  = s * (1.0f / 128.0f);
            float var = s2 * (1.0f / 128.0f) - mu * mu;
            float rs  = rsqrtf(var + LN_EPS);
            float4 y;
            y.x = (hv.x - mu) * rs * g4.x + be4.x;
            y.y = (hv.y - mu) * rs * g4.y + be4.y;
            y.z = (hv.z - mu) * rs * g4.z + be4.z;
            y.w = (hv.w - mu) * rs * g4.w + be4.w;
            reinterpret_cast<float4*>(out + (size_t)nd * D)[lane] = y;
        }
        __syncwarp();
    }
}

extern "C" void kernel_launch(void* const* d_in, const int* in_sizes, int n_in,
                              void* d_out, int out_size) {
    const float* x        = (const float*)d_in[0];
    const int*   ei       = (const int*)d_in[1];   // int32: JAX demotes int64
    const float* W1       = (const float*)d_in[2];
    const float* b1       = (const float*)d_in[3];
    const float* W2       = (const float*)d_in[4];
    const float* b2       = (const float*)d_in[5];
    const float* gamma    = (const float*)d_in[6];
    const float* beta     = (const float*)d_in[7];
    float* out            = (float*)d_out;

    int N = in_sizes[0] / D;
    int E = in_sizes[1] / 2;

    // zero scratch
    {
        int total = N * 32;
        int blocks = (total + 255) / 256;
        k_zero<<<blocks, 256>>>(N);
    }
    // edge scatter: one warp per edge
    {
        int blocks = (E + 7) / 8;
        k_edges<<<blocks, 256>>>(x, ei, E, N);
    }
    // fused node pipeline
    {
        size_t smem_bytes = (size_t)(D * H + H * D + H + D + D + D + 8 * D * 4 + 8 * H * 4) * sizeof(float);
        cudaFuncSetAttribute(k_nodes, cudaFuncAttributeMaxDynamicSharedMemorySize, (int)smem_bytes);
        k_nodes<<<296, 256, smem_bytes>>>(x, W1, b1, W2, b2, gamma, beta, out, N);
    }
}